// round 2
// baseline (speedup 1.0000x reference)
#include <cuda_runtime.h>

// TransD scoring: out = h - t + r + rp * ((hp.h) - (tp.t))
// One warp per TWO rows (doubles per-warp MLP: 12 front-batched LDG.128).
// lane i handles float4 element i of each row (D=128, D/4=32 == warp width).
// Output written with streaming hint (.cs) to keep L2 free for entity reuse.

static constexpr int DV4 = 32;  // 128 floats / 4

__device__ __forceinline__ float4 ldcs4(const float4* p) {
    return __ldcs(p);
}

__global__ __launch_bounds__(256) void transd_kernel(
    const int* __restrict__ head,
    const int* __restrict__ relation,
    const int* __restrict__ tail,
    const float4* __restrict__ ent_emb,
    const float4* __restrict__ ent_map_emb,
    const float4* __restrict__ rel_emb,
    const float4* __restrict__ rel_map_emb,
    float4* __restrict__ out,
    int B)
{
    int gtid = blockIdx.x * blockDim.x + threadIdx.x;
    int warp = gtid >> 5;
    int lane = gtid & 31;

    int row0 = warp * 2;
    int row1 = row0 + 1;
    if (row0 >= B) return;
    bool has1 = (row1 < B);

    // Index loads (read-once, streaming hint).
    int hi0 = __ldcs(&head[row0]);
    int ri0 = __ldcs(&relation[row0]);
    int ti0 = __ldcs(&tail[row0]);
    int hi1 = has1 ? __ldcs(&head[row1])     : hi0;
    int ri1 = has1 ? __ldcs(&relation[row1]) : ri0;
    int ti1 = has1 ? __ldcs(&tail[row1])     : ti0;

    long ho0 = (long)hi0 * DV4 + lane;
    long to0 = (long)ti0 * DV4 + lane;
    long ro0 = (long)ri0 * DV4 + lane;
    long ho1 = (long)hi1 * DV4 + lane;
    long to1 = (long)ti1 * DV4 + lane;
    long ro1 = (long)ri1 * DV4 + lane;

    // Front-batch all 12 independent loads for max MLP.
    float4 hv0 = __ldg(&ent_emb[ho0]);
    float4 hp0 = __ldg(&ent_map_emb[ho0]);
    float4 tv0 = __ldg(&ent_emb[to0]);
    float4 tp0 = __ldg(&ent_map_emb[to0]);
    float4 hv1 = __ldg(&ent_emb[ho1]);
    float4 hp1 = __ldg(&ent_map_emb[ho1]);
    float4 tv1 = __ldg(&ent_emb[to1]);
    float4 tp1 = __ldg(&ent_map_emb[to1]);
    float4 rv0 = __ldg(&rel_emb[ro0]);
    float4 rp0 = __ldg(&rel_map_emb[ro0]);
    float4 rv1 = __ldg(&rel_emb[ro1]);
    float4 rp1 = __ldg(&rel_map_emb[ro1]);

    // Per-lane partial dot products.
    float sh0 = hv0.x * hp0.x + hv0.y * hp0.y + hv0.z * hp0.z + hv0.w * hp0.w;
    float st0 = tv0.x * tp0.x + tv0.y * tp0.y + tv0.z * tp0.z + tv0.w * tp0.w;
    float sh1 = hv1.x * hp1.x + hv1.y * hp1.y + hv1.z * hp1.z + hv1.w * hp1.w;
    float st1 = tv1.x * tp1.x + tv1.y * tp1.y + tv1.z * tp1.z + tv1.w * tp1.w;

    // Combine before reduction: we only need (sh - st) per row.
    float s0 = sh0 - st0;
    float s1 = sh1 - st1;

    // Warp butterfly reduction (both rows interleaved).
    #pragma unroll
    for (int o = 16; o > 0; o >>= 1) {
        s0 += __shfl_xor_sync(0xffffffffu, s0, o);
        s1 += __shfl_xor_sync(0xffffffffu, s1, o);
    }

    float4 o0;
    o0.x = hv0.x - tv0.x + rv0.x + rp0.x * s0;
    o0.y = hv0.y - tv0.y + rv0.y + rp0.y * s0;
    o0.z = hv0.z - tv0.z + rv0.z + rp0.z * s0;
    o0.w = hv0.w - tv0.w + rv0.w + rp0.w * s0;
    __stcs(&out[(long)row0 * DV4 + lane], o0);

    if (has1) {
        float4 o1;
        o1.x = hv1.x - tv1.x + rv1.x + rp1.x * s1;
        o1.y = hv1.y - tv1.y + rv1.y + rp1.y * s1;
        o1.z = hv1.z - tv1.z + rv1.z + rp1.z * s1;
        o1.w = hv1.w - tv1.w + rv1.w + rp1.w * s1;
        __stcs(&out[(long)row1 * DV4 + lane], o1);
    }
}

extern "C" void kernel_launch(void* const* d_in, const int* in_sizes, int n_in,
                              void* d_out, int out_size)
{
    const int*    head    = (const int*)d_in[0];
    const int*    rel     = (const int*)d_in[1];
    const int*    tail    = (const int*)d_in[2];
    const float4* ent     = (const float4*)d_in[3];
    const float4* ent_map = (const float4*)d_in[4];
    const float4* rel_e   = (const float4*)d_in[5];
    const float4* rel_map = (const float4*)d_in[6];
    float4*       out     = (float4*)d_out;

    int B = in_sizes[0];
    // 256 threads = 8 warps = 16 rows per block
    int blocks = (B + 15) / 16;
    transd_kernel<<<blocks, 256>>>(head, rel, tail, ent, ent_map, rel_e, rel_map, out, B);
}

// round 4
// speedup vs baseline: 1.0165x; 1.0165x over previous
#include <cuda_runtime.h>

// TransD scoring: out = h - t + r + rp * ((hp.h) - (tp.t))
// One warp per row. lane i handles one float4 (D=128, D/4=32 == warp width).
// L2 policy: entity gathers evict_last via createpolicy+cache_hint (protect
// repeats in L2), output stores .cs (evict-first), index loads .cs.

static constexpr int DV4 = 32;  // 128 floats / 4

__device__ __forceinline__ float4 ldg_evict_last(const float4* p, unsigned long long pol) {
    float4 v;
    asm volatile("ld.global.nc.L2::cache_hint.v4.f32 {%0,%1,%2,%3}, [%4], %5;"
                 : "=f"(v.x), "=f"(v.y), "=f"(v.z), "=f"(v.w)
                 : "l"(p), "l"(pol));
    return v;
}

__global__ __launch_bounds__(256) void transd_kernel(
    const int* __restrict__ head,
    const int* __restrict__ relation,
    const int* __restrict__ tail,
    const float4* __restrict__ ent_emb,
    const float4* __restrict__ ent_map_emb,
    const float4* __restrict__ rel_emb,
    const float4* __restrict__ rel_map_emb,
    float4* __restrict__ out,
    int B)
{
    int gtid = blockIdx.x * blockDim.x + threadIdx.x;
    int row  = gtid >> 5;
    int lane = gtid & 31;
    if (row >= B) return;

    // L2 eviction policy: keep entity lines resident (evict_last, fraction 1.0).
    unsigned long long pol;
    asm volatile("createpolicy.fractional.L2::evict_last.b64 %0, 1.0;" : "=l"(pol));

    // Index loads: broadcast within warp; streamed (read once).
    int hi = __ldcs(&head[row]);
    int ri = __ldcs(&relation[row]);
    int ti = __ldcs(&tail[row]);

    long hoff = (long)hi * DV4 + lane;
    long toff = (long)ti * DV4 + lane;
    long roff = (long)ri * DV4 + lane;

    // Front-batch all 6 independent loads for MLP.
    float4 hv = ldg_evict_last(&ent_emb[hoff], pol);
    float4 hp = ldg_evict_last(&ent_map_emb[hoff], pol);
    float4 tv = ldg_evict_last(&ent_emb[toff], pol);
    float4 tp = ldg_evict_last(&ent_map_emb[toff], pol);
    // Relation tables are tiny (512KB each) — default caching keeps them hot.
    float4 rv = __ldg(&rel_emb[roff]);
    float4 rp = __ldg(&rel_map_emb[roff]);

    // Per-lane partial dot products; combine before reduction.
    float sh = hv.x * hp.x + hv.y * hp.y + hv.z * hp.z + hv.w * hp.w;
    float st = tv.x * tp.x + tv.y * tp.y + tv.z * tp.z + tv.w * tp.w;
    float s = sh - st;

    // Warp butterfly reduction.
    #pragma unroll
    for (int o = 16; o > 0; o >>= 1) {
        s += __shfl_xor_sync(0xffffffffu, s, o);
    }

    float4 o4;
    o4.x = hv.x - tv.x + rv.x + rp.x * s;
    o4.y = hv.y - tv.y + rv.y + rp.y * s;
    o4.z = hv.z - tv.z + rv.z + rp.z * s;
    o4.w = hv.w - tv.w + rv.w + rp.w * s;

    // Streaming store: don't pollute L2 with write data.
    __stcs(&out[(long)row * DV4 + lane], o4);
}

extern "C" void kernel_launch(void* const* d_in, const int* in_sizes, int n_in,
                              void* d_out, int out_size)
{
    const int*    head    = (const int*)d_in[0];
    const int*    rel     = (const int*)d_in[1];
    const int*    tail    = (const int*)d_in[2];
    const float4* ent     = (const float4*)d_in[3];
    const float4* ent_map = (const float4*)d_in[4];
    const float4* rel_e   = (const float4*)d_in[5];
    const float4* rel_map = (const float4*)d_in[6];
    float4*       out     = (float4*)d_out;

    int B = in_sizes[0];
    // 256 threads = 8 warps = 8 rows per block
    int blocks = (B + 7) / 8;
    transd_kernel<<<blocks, 256>>>(head, rel, tail, ent, ent_map, rel_e, rel_map, out, B);
}